// round 17
// baseline (speedup 1.0000x reference)
#include <cuda_runtime.h>
#include <cstdint>

#define TSEQ 512
#define BT   16
#define NCTA 128
#define NTHR 512

// dynamic smem layout (u32 word indices)
#define S_WIH0 0      // 4096 words: resident Wih0 bf16 A-frags [wm][mt][L][4]
#define S_H0F  4096   // 2 x 1024 words: ping-pong h0 bf16 B-frags [8kt][2nt][32L][2]
#define S_H1F  6144   // 2 x 1024 words: ping-pong h1 bf16 B-frags
#define S_XF   8192   // 2 x 128 words: x bf16 B-frags (double buffered)
#define SMEM_WORDS 8448
#define SMEM_BYTES (SMEM_WORDS*4)

// persistent device scratch
__device__ uint32_t g_WF[24*8*4*32*4];            // 393KB bf16 frag-major weights, q-major
__device__ uint32_t g_xB[(size_t)NCTA*TSEQ*128];  // 33MB bf16 x B-frags
__device__ float g_b[2][512];                     // fused biases

__device__ __forceinline__ uint32_t bf2(float a, float b){
    uint32_t r;
    asm("{.reg .b16 lo, hi;\n\tcvt.rn.bf16.f32 lo, %1;\n\tcvt.rn.bf16.f32 hi, %2;\n\t"
        "mov.b32 %0, {lo, hi};}" : "=r"(r) : "f"(a), "f"(b));
    return r;
}
__device__ __forceinline__ uint16_t bfr(float v){
    uint16_t r; asm("cvt.rn.bf16.f32 %0, %1;" : "=h"(r) : "f"(v)); return r;
}

// ---------------- setup: bf16 frag-major packing (unchanged layouts) --------
// q = m*8 + kt; m: 0=Whh0(seg0), 1=Wih1(seg1), 2=Whh1(seg2)
__global__ void setup_kernel(const float* __restrict__ x,
    const float* __restrict__ Whh0, const float* __restrict__ Wih1,
    const float* __restrict__ Whh1,
    const float* __restrict__ bih0, const float* __restrict__ bhh0,
    const float* __restrict__ bih1, const float* __restrict__ bhh1)
{
    long long idx0 = blockIdx.x*(long long)blockDim.x + threadIdx.x;
    long long stride = (long long)gridDim.x*blockDim.x;

    for (long long idx = idx0; idx < 98304; idx += stride){
        int i  = (int)(idx & 3);
        int L  = (int)((idx >> 2) & 31);
        int mt = (int)((idx >> 7) & 3);
        int w  = (int)((idx >> 9) & 7);
        int q  = (int)(idx >> 12);
        int m  = q >> 3, kt = q & 7;
        int gid = L >> 2, tig = L & 3;
        int row = mt*128 + 16*w + gid + (i&1)*8;
        int col = kt*16 + 2*tig + (i>>1)*8;
        const float* W = (m==0) ? Whh0 : (m==1) ? Wih1 : Whh1;
        g_WF[idx] = bf2(W[row*128 + col], W[row*128 + col + 1]);
    }
    for (long long idx = idx0; idx < (long long)NCTA*TSEQ*128; idx += stride){
        int cta = (int)(idx >> 16);
        int rem = (int)(idx & 65535);
        int t   = rem >> 7;
        int e   = rem & 127;
        int reg = e & 1, L = (e>>1)&31, nt = e>>6;
        int gid = L>>2, tig = L&3;
        int b = cta*BT + nt*8 + gid;
        int k0 = 2*tig + reg*8;
        float v0 = (k0   < 14) ? x[((size_t)b*TSEQ + t)*14 + k0    ] : 0.f;
        float v1 = (k0+1 < 14) ? x[((size_t)b*TSEQ + t)*14 + k0 + 1] : 0.f;
        g_xB[idx] = bf2(v0, v1);
    }
    for (long long n = idx0; n < 512; n += stride){
        g_b[0][n] = bih0[n] + bhh0[n];
        g_b[1][n] = bih1[n] + bhh1[n];
    }
}

// ---------------- device helpers -------------------------------------------
__device__ __forceinline__ void mma16(float* d, uint4 a, uint2 b){
    asm volatile("mma.sync.aligned.m16n8k16.row.col.f32.bf16.bf16.f32 "
        "{%0,%1,%2,%3}, {%4,%5,%6,%7}, {%8,%9}, {%0,%1,%2,%3};"
        : "+f"(d[0]), "+f"(d[1]), "+f"(d[2]), "+f"(d[3])
        : "r"(a.x), "r"(a.y), "r"(a.z), "r"(a.w), "r"(b.x), "r"(b.y));
}
__device__ __forceinline__ uint4 ldgA(int q, int wm, int mt, int L){
    const uint4* p = (const uint4*)g_WF;
    return __ldg(p + (((q*8 + wm)*4 + mt)*32 + L));
}
__device__ __forceinline__ float tanhapx(float x){
    float r; asm("tanh.approx.f32 %0, %1;" : "=f"(r) : "f"(x)); return r;
}
__device__ __forceinline__ float sigapx(float x){
    return fmaf(tanhapx(0.5f*x), 0.5f, 0.5f);
}
__device__ __forceinline__ void cp_x(uint32_t* dst, const uint32_t* src, int tid){
    if (tid < 128){
        unsigned d = (unsigned)__cvta_generic_to_shared(dst + tid);
        asm volatile("cp.async.ca.shared.global [%0], [%1], 4;" :: "r"(d), "l"(src + tid));
    }
}
__device__ __forceinline__ void cp_commit(){ asm volatile("cp.async.commit_group;"); }
__device__ __forceinline__ void cp_wait0(){ asm volatile("cp.async.wait_group 0;"); }

__device__ __forceinline__ void initacc(float (&acc)[4][4], const float* bs){
    #pragma unroll
    for (int g = 0; g < 4; g++){
        acc[g][0] = bs[g*2];   acc[g][1] = bs[g*2];
        acc[g][2] = bs[g*2+1]; acc[g][3] = bs[g*2+1];
    }
}

// one 8-kt GEMM segment of the flat 24-q ring; A ring depth 4, refill q+4 mod 24
template<int SEG>
__device__ __forceinline__ void gemm_seg(float (&acc)[4][4], uint4 (&A)[4][4],
                                         const uint32_t* __restrict__ hF,
                                         int wm, int wn, int L)
{
    uint2 B[2];
    B[0] = *(const uint2*)(hF + (wn*32 + L)*2);
    #pragma unroll
    for (int kt = 0; kt < 8; kt++){
        const int q  = SEG*8 + kt;
        const int qn = (q + 4) % 24;
        if (kt < 7)
            B[(kt+1)&1] = *(const uint2*)(hF + (((kt+1)*2 + wn)*32 + L)*2);
        #pragma unroll
        for (int mt = 0; mt < 4; mt++)
            mma16(acc[mt], A[q&3][mt], B[kt&1]);
        #pragma unroll
        for (int mt = 0; mt < 4; mt++)
            A[q&3][mt] = ldgA(qn, wm, mt, L);
    }
}

// x projection: A = resident Wih0 frags (smem), single K=16 tile
__device__ __forceinline__ void gemm_x(float (&acc)[4][4], const uint32_t* smW,
                                       const uint32_t* xf, int wm, int wn, int L)
{
    uint2 b = *(const uint2*)(xf + (wn*32 + L)*2);
    #pragma unroll
    for (int mt = 0; mt < 4; mt++){
        uint4 a = *(const uint4*)(smW + ((wm*4 + mt)*32 + L)*4);
        mma16(acc[mt], a, b);
    }
}

// LSTM cell epilogue: 4 thread-local cells (2 units x 2 batch) -> ping-pong dst
__device__ __forceinline__ void epi(float (&acc)[4][4], float* cst,
                                    uint32_t* hFdst, int wm, int wn, int L)
{
    uint16_t* hs = (uint16_t*)hFdst;
    const int gid = L >> 2, tig = L & 3;
    #pragma unroll
    for (int hh = 0; hh < 2; hh++)
        #pragma unroll
        for (int j = 0; j < 2; j++){
            int d = hh*2 + j;
            float i_ = sigapx(acc[0][d]);
            float f_ = sigapx(acc[1][d]);
            float g_ = tanhapx(acc[2][d]);
            float o_ = sigapx(acc[3][d]);
            int ci = hh*2 + j;
            float cc = f_*cst[ci] + i_*g_;
            cst[ci] = cc;
            float h = o_*tanhapx(cc);
            // unit u = 16wm + gid + 8hh ; batch b = wn*8 + 2tig + j
            int Lp = (2*tig + j)*4 + (gid >> 1);
            int off16 = ((wm*2 + wn)*32 + Lp)*4 + hh*2 + (gid & 1);
            hs[off16] = bfr(h);
        }
}

// ---------------- main persistent kernel ------------------------------------
__global__ void __launch_bounds__(NTHR, 1)
lstm_mma_kernel(const float* __restrict__ Wih0, const float* __restrict__ Wfc,
                const float* __restrict__ bfc, float* __restrict__ out)
{
    extern __shared__ uint32_t sm[];
    const int tid = threadIdx.x, w = tid >> 5, L = tid & 31;
    const int wm = w & 7, wn = w >> 3;

    // resident Wih0 bf16 A-frags [wm][mt][L][4], K padded 14->16
    for (int idx = tid; idx < 4096; idx += NTHR){
        int i = idx & 3, l = (idx>>2)&31, mt = (idx>>7)&3, ww = idx>>9;
        int gid = l>>2, tig = l&3;
        int row = mt*128 + 16*ww + gid + (i&1)*8;
        int c0 = 2*tig + (i>>1)*8;
        float v0 = (c0   < 14) ? Wih0[row*14 + c0    ] : 0.f;
        float v1 = (c0+1 < 14) ? Wih0[row*14 + c0 + 1] : 0.f;
        sm[S_WIH0 + idx] = bf2(v0, v1);
    }
    for (int idx = tid; idx < 4096; idx += NTHR) sm[S_H0F + idx] = 0u;  // all h buffers

    const int u_lo = 16*wm + (L>>2), u_hi = u_lo + 8;
    float bs0[8], bs1[8];
    #pragma unroll
    for (int g = 0; g < 4; g++){
        bs0[g*2]   = g_b[0][g*128 + u_lo];
        bs0[g*2+1] = g_b[0][g*128 + u_hi];
        bs1[g*2]   = g_b[1][g*128 + u_lo];
        bs1[g*2+1] = g_b[1][g*128 + u_hi];
    }
    float c0[4], c1[4];
    #pragma unroll
    for (int i = 0; i < 4; i++){ c0[i] = 0.f; c1[i] = 0.f; }

    const uint32_t* xsrc = g_xB + (size_t)blockIdx.x*TSEQ*128;
    cp_x(sm + S_XF, xsrc, tid);
    cp_commit();
    cp_wait0();
    __syncthreads();

    float acc[4][4];
    uint4 A[4][4];
    #pragma unroll
    for (int q = 0; q < 4; q++)
        #pragma unroll
        for (int mt = 0; mt < 4; mt++)
            A[q][mt] = ldgA(q, wm, mt, L);

    for (int t = 0; t < TSEQ; t++){
        const int p = t & 1, pn = p ^ 1;
        // ---- phase 1: bias0 + x-proj(t) + Whh0*h0[p] ; epi0 -> h0[pn] ----
        initacc(acc, bs0);
        gemm_x(acc, sm + S_WIH0, sm + S_XF + p*128, wm, wn, L);
        gemm_seg<0>(acc, A, sm + S_H0F + p*1024, wm, wn, L);
        epi(acc, c0, sm + S_H0F + pn*1024, wm, wn, L);
        __syncthreads();   // h0[pn] visible; h0[p]/x[p] reads done

        // ---- phase 2: bias1 + Wih1*h0[pn] + Whh1*h1[p] ; epi1 -> h1[pn] ----
        initacc(acc, bs1);
        if (t + 1 < TSEQ){
            cp_x(sm + S_XF + pn*128, xsrc + (size_t)(t+1)*128, tid);
            cp_commit();
        }
        gemm_seg<1>(acc, A, sm + S_H0F + pn*1024, wm, wn, L);
        gemm_seg<2>(acc, A, sm + S_H1F + p*1024, wm, wn, L);
        epi(acc, c1, sm + S_H1F + pn*1024, wm, wn, L);
        cp_wait0();
        __syncthreads();   // h1[pn] + x[pn] visible; h1[p] reads done
    }

    // ---- FC + sigmoid on final h1 (buffer 0 after t=511 writes pn=0) ----
    {
        const uint16_t* hs = (const uint16_t*)(sm + S_H1F);   // TSEQ even -> buf 0
        float bias = bfc[0];
        if (w < BT){
            int b = w;
            float s = 0.f;
            #pragma unroll
            for (int qq = 0; qq < 4; qq++){
                int u = L + 32*qq;
                int kt = u >> 4, k = u & 15;
                int reg = k >> 3, kk = k & 7;
                int Lp = (b & 7)*4 + (kk >> 1);
                int off16 = ((kt*2 + (b>>3))*32 + Lp)*4 + reg*2 + (kk & 1);
                float hv = __uint_as_float(((uint32_t)hs[off16]) << 16);
                s += hv * __ldg(Wfc + u);
            }
            #pragma unroll
            for (int off = 16; off; off >>= 1) s += __shfl_xor_sync(0xffffffffu, s, off);
            if (L == 0) out[blockIdx.x*BT + b] = sigapx(s + bias);
        }
    }
}

// ---------------- launch ----------------------------------------------------
extern "C" void kernel_launch(void* const* d_in, const int* in_sizes, int n_in,
                              void* d_out, int out_size)
{
    const float* x    = (const float*)d_in[0];
    const float* Wih0 = (const float*)d_in[1];
    const float* Whh0 = (const float*)d_in[2];
    const float* bih0 = (const float*)d_in[3];
    const float* bhh0 = (const float*)d_in[4];
    const float* Wih1 = (const float*)d_in[5];
    const float* Whh1 = (const float*)d_in[6];
    const float* bih1 = (const float*)d_in[7];
    const float* bhh1 = (const float*)d_in[8];
    const float* Wfc  = (const float*)d_in[9];
    const float* bfc  = (const float*)d_in[10];

    cudaFuncSetAttribute(lstm_mma_kernel,
                         cudaFuncAttributeMaxDynamicSharedMemorySize, SMEM_BYTES);

    setup_kernel<<<4096, 256>>>(x, Whh0, Wih1, Whh1, bih0, bhh0, bih1, bhh1);
    lstm_mma_kernel<<<NCTA, NTHR, SMEM_BYTES>>>(Wih0, Wfc, bfc, (float*)d_out);
}